// round 14
// baseline (speedup 1.0000x reference)
#include <cuda_runtime.h>
#include <cstdint>

// Problem constants
#define BB 4
#define SS 8192
#define DD 1024
#define KK 16
#define MTOT (BB * SS)        // 32768 tokens
#define TS_CHUNKS 64
#define TS_SLEN (SS / TS_CHUNKS)   // 128
#define MKD (BB * KK * DD)    // 65536
#define SG_ECHUNKS 32         // smallgemm e-chunks (32 e each)

// ---------------- scratch (device globals; no allocations) ------------------
__device__ float g_aff [(size_t)MTOT * KK];            // 2 MB
__device__ float g_tsp [(size_t)TS_CHUNKS * MKD];      // 16 MB  (ts partials)
__device__ float g_ts  [(size_t)MKD];                  // 256 KB (aff^T @ tok)
__device__ float g_ssp [(size_t)SG_ECHUNKS * MKD];     // 8 MB   (partials, reused)
__device__ float g_ss  [(size_t)MKD];                  // 256 KB (ts @ W_v)
__device__ float g_ssw [(size_t)MKD];                  // 256 KB (ss @ W_o)
__device__ float g_params[32];                         // csq[16], m[16]

// ---------------- packed f32x2 helpers ---------------------------------------
#define FMA2(d, a, b) \
    asm("fma.rn.f32x2 %0, %1, %2, %0;" : "+l"(d) : "l"(a), "l"(b))
#define PACK2(dst, lo, hi) \
    asm("mov.b64 %0, {%1, %2};" : "=l"(dst) \
        : "r"(__float_as_uint(lo)), "r"(__float_as_uint(hi)))

typedef unsigned long long ull;

__device__ __forceinline__ uint32_t smem_to_u32(const void* smem_ptr) {
    uint32_t addr;
    asm("{ .reg .u64 tmp; cvta.to.shared.u64 tmp, %1; cvt.u32.u64 %0, tmp; }"
        : "=r"(addr) : "l"(smem_ptr));
    return addr;
}
__device__ __forceinline__ uint32_t f2tf32(float x) {
    uint32_t r;
    asm("cvt.rn.tf32.f32 %0, %1;" : "=r"(r) : "f"(x));
    return r;
}
#define CP_ASYNC16(dst_u32, src_ptr) \
    asm volatile("cp.async.ca.shared.global [%0], [%1], 16;" \
        :: "r"(dst_u32), "l"(src_ptr) : "memory")
#define CP_COMMIT() asm volatile("cp.async.commit_group;" ::: "memory")
#define CP_WAIT0()  asm volatile("cp.async.wait_group 0;" ::: "memory")
#define CP_WAIT1()  asm volatile("cp.async.wait_group 1;" ::: "memory")

__device__ __forceinline__ void mma_tf32(float* c, const uint32_t* a, const uint32_t* b) {
    asm volatile(
        "mma.sync.aligned.m16n8k8.row.col.f32.tf32.tf32.f32 "
        "{%0,%1,%2,%3}, {%4,%5,%6,%7}, {%8,%9}, {%0,%1,%2,%3};\n"
        : "+f"(c[0]), "+f"(c[1]), "+f"(c[2]), "+f"(c[3])
        : "r"(a[0]), "r"(a[1]), "r"(a[2]), "r"(a[3]), "r"(b[0]), "r"(b[1]));
}

// ======================= kernel 0: per-splat params ==========================
__global__ __launch_bounds__(512)
void params_kernel(const float* __restrict__ centers,
                   const float* __restrict__ log_scales)
{
    const int w    = threadIdx.x >> 5;
    const int lane = threadIdx.x & 31;
    float s = 0.f;
    const float* c = centers + (size_t)w * DD;
    for (int d = lane; d < DD; d += 32) {
        float v = c[d];
        s = fmaf(v, v, s);
    }
    #pragma unroll
    for (int off = 16; off; off >>= 1)
        s += __shfl_xor_sync(0xffffffffu, s, off);
    if (lane == 0) {
        g_params[w] = s;
        float sc = expf(log_scales[w]);
        sc = fminf(fmaxf(sc, 0.1f), 2.0f);
        g_params[16 + w] = -0.5f / (sc * sc);
    }
}

// ======================= fused cross/aff (mma) + ts partials =================
// grid (TS_CHUNKS, BB), block 256 (8 warps). Block owns 128 tokens.
// Phase A: cross = tok @ centers^T via tf32 mma.sync, BK=64 double-buffered.
// Phase B: ts partial accumulation (token chunk re-read).
#define XLDP 68                        // 64 k + 4 pad (floats)
#define XA_WORDS (128 * XLDP)          // 8704 floats
#define XB_WORDS (16 * XLDP)           // 1088 floats
#define XBUF (XA_WORDS + XB_WORDS)     // 9792 floats = 39168 B per buffer
#define NKC (DD / 64)                  // 16 iterations
#define FUSED_SMEM (2 * XBUF * 4)      // 78336 B dynamic

__device__ __forceinline__ void fused_issue_stage(
    const float* __restrict__ tok, const float* __restrict__ centers,
    uint32_t buf_base, int bm, int k0, int tid)
{
    // A tile: 128 rows x 64 k = 2048 float4 -> 8 per thread
    #pragma unroll
    for (int i = 0; i < 8; i++) {
        const int id  = tid + i * 256;
        const int row = id >> 4;          // 16 float4 per row
        const int c4  = id & 15;
        CP_ASYNC16(buf_base + (uint32_t)(row * XLDP + c4 * 4) * 4,
                   tok + (size_t)(bm + row) * DD + k0 + c4 * 4);
    }
    // B tile: 16 rows x 64 k = 256 float4 -> 1 per thread
    {
        const int row = tid >> 4;
        const int c4  = tid & 15;
        CP_ASYNC16(buf_base + (uint32_t)(XA_WORDS + row * XLDP + c4 * 4) * 4,
                   centers + (size_t)row * DD + k0 + c4 * 4);
    }
}

__global__ __launch_bounds__(256)
void fused_cross_aff_ts_kernel(const float* __restrict__ tok,
                               const float* __restrict__ centers)
{
    extern __shared__ float xs[];      // 2 buffers; aliased as saff after phase A
    float2 (*saff)[KK] = reinterpret_cast<float2(*)[KK]>(xs);  // [128][16]

    const int tid  = threadIdx.x;
    const int w    = tid >> 5;
    const int lane = tid & 31;
    const int grp  = lane >> 2;        // 0..7
    const int tig  = lane & 3;         // 0..3
    const int ck   = blockIdx.x;
    const int b    = blockIdx.y;
    const int s0   = ck * TS_SLEN;
    const int bm   = b * SS + s0;      // global token base
    const int wm16 = w * 16;

    const uint32_t sbase = smem_to_u32(xs);

    // ---------------- Phase A: mma cross products ----------------
    float acc[2][4];
    #pragma unroll
    for (int nf = 0; nf < 2; nf++)
        #pragma unroll
        for (int q = 0; q < 4; q++) acc[nf][q] = 0.f;
    float sq0 = 0.f, sq1 = 0.f;

    fused_issue_stage(tok, centers, sbase, bm, 0, tid);
    CP_COMMIT();

    for (int kc = 0; kc < NKC; kc++) {
        const int cur = kc & 1;
        if (kc + 1 < NKC) {
            const int nxt = cur ^ 1;
            fused_issue_stage(tok, centers, sbase + (uint32_t)nxt * XBUF * 4,
                              bm, (kc + 1) * 64, tid);
            CP_COMMIT();
            CP_WAIT1();
        } else {
            CP_WAIT0();
        }
        __syncthreads();

        const float* As = xs + (size_t)cur * XBUF;
        const float* Bs = As + XA_WORDS;

        #pragma unroll
        for (int ks = 0; ks < 8; ks++) {
            const int kq = ks * 8 + tig;
            const float a0 = As[(wm16 + grp)     * XLDP + kq];
            const float a1 = As[(wm16 + grp + 8) * XLDP + kq];
            const float a2 = As[(wm16 + grp)     * XLDP + kq + 4];
            const float a3 = As[(wm16 + grp + 8) * XLDP + kq + 4];
            sq0 = fmaf(a0, a0, fmaf(a2, a2, sq0));
            sq1 = fmaf(a1, a1, fmaf(a3, a3, sq1));
            uint32_t af[4] = {f2tf32(a0), f2tf32(a1), f2tf32(a2), f2tf32(a3)};
            #pragma unroll
            for (int nf = 0; nf < 2; nf++) {
                const int cidx = nf * 8 + grp;
                uint32_t bf[2] = {f2tf32(Bs[cidx * XLDP + kq]),
                                  f2tf32(Bs[cidx * XLDP + kq + 4])};
                mma_tf32(acc[nf], af, bf);
            }
        }
        __syncthreads();
    }

    // tsq: reduce over cols within each quad
    sq0 += __shfl_xor_sync(0xffffffffu, sq0, 1);
    sq0 += __shfl_xor_sync(0xffffffffu, sq0, 2);
    sq1 += __shfl_xor_sync(0xffffffffu, sq1, 1);
    sq1 += __shfl_xor_sync(0xffffffffu, sq1, 2);

    float e0[4], e1[4];
    #pragma unroll
    for (int nf = 0; nf < 2; nf++) {
        #pragma unroll
        for (int j = 0; j < 2; j++) {
            const int col = nf * 8 + tig * 2 + j;
            const float csq = g_params[col];
            const float m   = g_params[16 + col];
            float d0 = fmaxf(sq0 - 2.f * acc[nf][j]     + csq, 0.f);
            float d1 = fmaxf(sq1 - 2.f * acc[nf][2 + j] + csq, 0.f);
            e0[nf * 2 + j] = expf(m * d0);
            e1[nf * 2 + j] = expf(m * d1);
        }
    }
    float es0 = e0[0] + e0[1] + e0[2] + e0[3];
    float es1 = e1[0] + e1[1] + e1[2] + e1[3];
    es0 += __shfl_xor_sync(0xffffffffu, es0, 1);
    es0 += __shfl_xor_sync(0xffffffffu, es0, 2);
    es1 += __shfl_xor_sync(0xffffffffu, es1, 1);
    es1 += __shfl_xor_sync(0xffffffffu, es1, 2);
    const float r0 = 1.f / (es0 + 1e-8f);
    const float r1 = 1.f / (es1 + 1e-8f);

    // write aff to global + smem (aliased over dead xs)
    const int lt0 = wm16 + grp;            // local token 0..127
    #pragma unroll
    for (int nf = 0; nf < 2; nf++) {
        const int col = nf * 8 + tig * 2;
        float v00 = e0[nf * 2] * r0, v01 = e0[nf * 2 + 1] * r0;
        float v10 = e1[nf * 2] * r1, v11 = e1[nf * 2 + 1] * r1;
        *reinterpret_cast<float2*>(g_aff + (size_t)(bm + lt0) * KK + col) =
            make_float2(v00, v01);
        *reinterpret_cast<float2*>(g_aff + (size_t)(bm + lt0 + 8) * KK + col) =
            make_float2(v10, v11);
        saff[lt0][col]     = make_float2(v00, v00);
        saff[lt0][col + 1] = make_float2(v01, v01);
        saff[lt0 + 8][col]     = make_float2(v10, v10);
        saff[lt0 + 8][col + 1] = make_float2(v11, v11);
    }
    __syncthreads();

    // ---------------- Phase B: ts partial accumulation ----------------------
    const int d = tid * 4;
    const float* tp = tok + (size_t)bm * DD + d;

    ull tacc[KK][2];
    #pragma unroll
    for (int k = 0; k < KK; k++) { tacc[k][0] = 0ull; tacc[k][1] = 0ull; }

    #pragma unroll 2
    for (int s = 0; s < TS_SLEN; s++) {
        float4 v = *reinterpret_cast<const float4*>(tp + (size_t)s * DD);
        ull vlo, vhi;
        PACK2(vlo, v.x, v.y);
        PACK2(vhi, v.z, v.w);
        #pragma unroll
        for (int k = 0; k < KK; k++) {
            ull a = *reinterpret_cast<const ull*>(&saff[s][k]);
            FMA2(tacc[k][0], a, vlo);
            FMA2(tacc[k][1], a, vhi);
        }
    }

    float* op = g_tsp + (size_t)ck * MKD + ((size_t)b * KK) * DD + d;
    #pragma unroll
    for (int k = 0; k < KK; k++)
        *reinterpret_cast<ulonglong2*>(op + (size_t)k * DD) =
            make_ulonglong2(tacc[k][0], tacc[k][1]);
}

// ======================= reduce stage 1: 64 -> 8 partials ====================
__global__ __launch_bounds__(256)
void reduce_stage1_kernel(const float4* __restrict__ src, float4* __restrict__ dst,
                          int len4)
{
    const int i  = blockIdx.x * 256 + threadIdx.x;
    const int pg = blockIdx.y;
    float4 a0 = make_float4(0,0,0,0), a1 = a0;
    #pragma unroll
    for (int q = 0; q < 8; q += 2) {
        float4 v0 = src[(size_t)(pg * 8 + q)     * len4 + i];
        float4 v1 = src[(size_t)(pg * 8 + q + 1) * len4 + i];
        a0.x += v0.x; a0.y += v0.y; a0.z += v0.z; a0.w += v0.w;
        a1.x += v1.x; a1.y += v1.y; a1.z += v1.z; a1.w += v1.w;
    }
    dst[(size_t)pg * len4 + i] = make_float4(a0.x + a1.x, a0.y + a1.y,
                                             a0.z + a1.z, a0.w + a1.w);
}

// ======================= vectorized partial reduce ===========================
__global__ __launch_bounds__(256)
void reduce4_kernel(const float4* __restrict__ src, float4* __restrict__ dst,
                    int np, int len4)
{
    const int i = blockIdx.x * 256 + threadIdx.x;
    if (i >= len4) return;
    float4 a0 = make_float4(0,0,0,0), a1 = a0, a2 = a0, a3 = a0;
    int p = 0;
    for (; p + 4 <= np; p += 4) {
        float4 v0 = src[(size_t)(p + 0) * len4 + i];
        float4 v1 = src[(size_t)(p + 1) * len4 + i];
        float4 v2 = src[(size_t)(p + 2) * len4 + i];
        float4 v3 = src[(size_t)(p + 3) * len4 + i];
        a0.x += v0.x; a0.y += v0.y; a0.z += v0.z; a0.w += v0.w;
        a1.x += v1.x; a1.y += v1.y; a1.z += v1.z; a1.w += v1.w;
        a2.x += v2.x; a2.y += v2.y; a2.z += v2.z; a2.w += v2.w;
        a3.x += v3.x; a3.y += v3.y; a3.z += v3.z; a3.w += v3.w;
    }
    for (; p < np; p++) {
        float4 v = src[(size_t)p * len4 + i];
        a0.x += v.x; a0.y += v.y; a0.z += v.z; a0.w += v.w;
    }
    dst[i] = make_float4(a0.x + a1.x + a2.x + a3.x,
                         a0.y + a1.y + a2.y + a3.y,
                         a0.z + a1.z + a2.z + a3.z,
                         a0.w + a1.w + a2.w + a3.w);
}

// ======================= mini GEMM (R11) =====================================
__global__ __launch_bounds__(256)
void smallgemm_kernel(const float* __restrict__ M64, const float* __restrict__ W)
{
    __shared__ float se[32][66];   // [e][m], padded
    const int tid = threadIdx.x;
    const int n0  = blockIdx.x * 64;
    const int e0  = blockIdx.y * 32;

    {
        const int m  = tid >> 2;
        const int ee = (tid & 3) * 8;
        const float* mp = M64 + (size_t)m * DD + e0 + ee;
        float4 v0 = *reinterpret_cast<const float4*>(mp);
        float4 v1 = *reinterpret_cast<const float4*>(mp + 4);
        se[ee + 0][m] = v0.x; se[ee + 1][m] = v0.y;
        se[ee + 2][m] = v0.z; se[ee + 3][m] = v0.w;
        se[ee + 4][m] = v1.x; se[ee + 5][m] = v1.y;
        se[ee + 6][m] = v1.z; se[ee + 7][m] = v1.w;
    }
    __syncthreads();

    const int nq = tid & 63;
    const int mg = tid >> 6;
    const float* wp = W + (size_t)e0 * DD + n0 + nq;

    ull acc[8];
    #pragma unroll
    for (int j = 0; j < 8; j++) acc[j] = 0ull;

    float wv[4], nv[4];
    #pragma unroll
    for (int q = 0; q < 4; q++) wv[q] = wp[(size_t)q * DD];

    #pragma unroll
    for (int e = 0; e < 32; e += 4) {
        if (e + 4 < 32) {
            #pragma unroll
            for (int q = 0; q < 4; q++) nv[q] = wp[(size_t)(e + 4 + q) * DD];
        }
        #pragma unroll
        for (int q = 0; q < 4; q++) {
            ull wd;
            PACK2(wd, wv[q], wv[q]);
            #pragma unroll
            for (int j = 0; j < 8; j++) {
                ull a = *reinterpret_cast<const ull*>(&se[e + q][mg * 16 + 2 * j]);
                FMA2(acc[j], a, wd);
            }
        }
        #pragma unroll
        for (int q = 0; q < 4; q++) wv[q] = nv[q];
    }

    float* dst = g_ssp + (size_t)blockIdx.y * MKD + n0 + nq;
    #pragma unroll
    for (int j = 0; j < 8; j++) {
        float2 p = *reinterpret_cast<float2*>(&acc[j]);
        dst[(size_t)(mg * 16 + 2 * j)     * DD] = p.x;
        dst[(size_t)(mg * 16 + 2 * j + 1) * DD] = p.y;
    }
}

// ======================= out = aff @ ssw (token-pair packed) =================
__global__ __launch_bounds__(256)
void out_mix_kernel(float* __restrict__ out)
{
    __shared__ float saT[KK][128];   // 8KB, aff transposed
    const int tid  = threadIdx.x;
    const int wid  = tid >> 5;
    const int lane = tid & 31;
    const int b    = blockIdx.y;
    const int s0   = blockIdx.x * 128;

    {
        const float* ap = g_aff + ((size_t)b * SS + s0) * KK;
        #pragma unroll
        for (int it = 0; it < 2; it++) {
            const int i = tid + it * 256;
            float4 v = *reinterpret_cast<const float4*>(ap + i * 4);
            const int t  = i >> 2;
            const int kg = (i & 3) * 4;
            saT[kg + 0][t] = v.x;
            saT[kg + 1][t] = v.y;
            saT[kg + 2][t] = v.z;
            saT[kg + 3][t] = v.w;
        }
    }
    __syncthreads();

    #pragma unroll 1
    for (int pass = 0; pass < 2; pass++) {
        const int d0 = pass * 512 + wid * 64 + lane * 2;

        ull wd0[KK], wd1[KK];
        #pragma unroll
        for (int k = 0; k < KK; k++) {
            float2 wv = *reinterpret_cast<const float2*>(
                g_ssw + ((size_t)(b * KK + k)) * DD + d0);
            PACK2(wd0[k], wv.x, wv.x);
            PACK2(wd1[k], wv.y, wv.y);
        }

        float* op = out + ((size_t)b * SS + s0) * DD + d0;

        #pragma unroll 2
        for (int t = 0; t < 128; t += 2) {
            ull acc0 = 0ull, acc1 = 0ull;
            #pragma unroll
            for (int k = 0; k < KK; k++) {
                ull a = *reinterpret_cast<const ull*>(&saT[k][t]);
                FMA2(acc0, a, wd0[k]);
                FMA2(acc1, a, wd1[k]);
            }
            float2 p0 = *reinterpret_cast<float2*>(&acc0);
            float2 p1 = *reinterpret_cast<float2*>(&acc1);
            *reinterpret_cast<float2*>(op + (size_t)t * DD)       = make_float2(p0.x, p1.x);
            *reinterpret_cast<float2*>(op + (size_t)(t + 1) * DD) = make_float2(p0.y, p1.y);
        }
    }
}

// ======================= launch ==============================================
extern "C" void kernel_launch(void* const* d_in, const int* in_sizes, int n_in,
                              void* d_out, int out_size)
{
    const float* tok     = (const float*)d_in[0];
    const float* centers = (const float*)d_in[1];
    const float* logs    = (const float*)d_in[2];
    const float* Wv      = (const float*)d_in[3];
    const float* Wo      = (const float*)d_in[4];
    float* out = (float*)d_out;

    float *tsp, *ts, *ssp, *ss, *ssw;
    cudaGetSymbolAddress((void**)&tsp, g_tsp);
    cudaGetSymbolAddress((void**)&ts,  g_ts);
    cudaGetSymbolAddress((void**)&ssp, g_ssp);
    cudaGetSymbolAddress((void**)&ss,  g_ss);
    cudaGetSymbolAddress((void**)&ssw, g_ssw);

    const int len4 = MKD / 4;   // 16384

    cudaFuncSetAttribute(fused_cross_aff_ts_kernel,
                         cudaFuncAttributeMaxDynamicSharedMemorySize, FUSED_SMEM);

    params_kernel<<<1, 512>>>(centers, logs);

    // affinities (mma) + ts partials, single token pass
    fused_cross_aff_ts_kernel<<<dim3(TS_CHUNKS, BB), 256, FUSED_SMEM>>>(tok, centers);

    // ts reduce: 64 -> 8 (into g_ssp) -> 1
    reduce_stage1_kernel<<<dim3(len4 / 256, 8), 256>>>(
        (const float4*)tsp, (float4*)ssp, len4);
    reduce4_kernel<<<len4 / 256, 256>>>(
        (const float4*)ssp, (float4*)ts, 8, len4);

    // ss = ts @ W_v
    smallgemm_kernel<<<dim3(16, SG_ECHUNKS), 256>>>(ts, Wv);
    reduce4_kernel<<<len4 / 256, 256>>>(
        (const float4*)ssp, (float4*)ss, SG_ECHUNKS, len4);

    // ssw = ss @ W_o
    smallgemm_kernel<<<dim3(16, SG_ECHUNKS), 256>>>(ss, Wo);
    reduce4_kernel<<<len4 / 256, 256>>>(
        (const float4*)ssp, (float4*)ssw, SG_ECHUNKS, len4);

    // out = aff @ ssw
    out_mix_kernel<<<dim3(SS / 128, BB), 256>>>(out);
}

// round 15
// speedup vs baseline: 1.0436x; 1.0436x over previous
#include <cuda_runtime.h>
#include <cstdint>

// Problem constants
#define BB 4
#define SS 8192
#define DD 1024
#define KK 16
#define MTOT (BB * SS)        // 32768 tokens
#define TS_CHUNKS 64
#define TS_SLEN (SS / TS_CHUNKS)   // 128
#define MKD (BB * KK * DD)    // 65536
#define SG_ECHUNKS 32         // smallgemm e-chunks (32 e each)

// ---------------- scratch (device globals; no allocations) ------------------
__device__ float g_aff [(size_t)MTOT * KK];            // 2 MB
__device__ float g_tsp [(size_t)TS_CHUNKS * MKD];      // 16 MB  (ts partials)
__device__ float g_ts  [(size_t)MKD];                  // 256 KB (aff^T @ tok)
__device__ float g_ssp [(size_t)SG_ECHUNKS * MKD];     // 8 MB   (partials, reused)
__device__ float g_ss  [(size_t)MKD];                  // 256 KB (ts @ W_v)
__device__ float g_ssw [(size_t)MKD];                  // 256 KB (ss @ W_o)
__device__ float g_params[32];                         // csq[16], m[16]

// ---------------- packed f32x2 helpers ---------------------------------------
#define FMA2(d, a, b) \
    asm("fma.rn.f32x2 %0, %1, %2, %0;" : "+l"(d) : "l"(a), "l"(b))
#define PACK2(dst, lo, hi) \
    asm("mov.b64 %0, {%1, %2};" : "=l"(dst) \
        : "r"(__float_as_uint(lo)), "r"(__float_as_uint(hi)))

typedef unsigned long long ull;

__device__ __forceinline__ uint32_t smem_to_u32(const void* smem_ptr) {
    uint32_t addr;
    asm("{ .reg .u64 tmp; cvta.to.shared.u64 tmp, %1; cvt.u32.u64 %0, tmp; }"
        : "=r"(addr) : "l"(smem_ptr));
    return addr;
}
__device__ __forceinline__ uint32_t f2tf32(float x) {
    uint32_t r;
    asm("cvt.rn.tf32.f32 %0, %1;" : "=r"(r) : "f"(x));
    return r;
}
#define CP_ASYNC16(dst_u32, src_ptr) \
    asm volatile("cp.async.ca.shared.global [%0], [%1], 16;" \
        :: "r"(dst_u32), "l"(src_ptr) : "memory")
#define CP_COMMIT() asm volatile("cp.async.commit_group;" ::: "memory")
#define CP_WAIT0()  asm volatile("cp.async.wait_group 0;" ::: "memory")
#define CP_WAIT1()  asm volatile("cp.async.wait_group 1;" ::: "memory")

__device__ __forceinline__ void mma_tf32(float* c, const uint32_t* a, const uint32_t* b) {
    asm volatile(
        "mma.sync.aligned.m16n8k8.row.col.f32.tf32.tf32.f32 "
        "{%0,%1,%2,%3}, {%4,%5,%6,%7}, {%8,%9}, {%0,%1,%2,%3};\n"
        : "+f"(c[0]), "+f"(c[1]), "+f"(c[2]), "+f"(c[3])
        : "r"(a[0]), "r"(a[1]), "r"(a[2]), "r"(a[3]), "r"(b[0]), "r"(b[1]));
}

// ======================= kernel 0: per-splat params ==========================
__global__ __launch_bounds__(512)
void params_kernel(const float* __restrict__ centers,
                   const float* __restrict__ log_scales)
{
    const int w    = threadIdx.x >> 5;
    const int lane = threadIdx.x & 31;
    float s = 0.f;
    const float* c = centers + (size_t)w * DD;
    for (int d = lane; d < DD; d += 32) {
        float v = c[d];
        s = fmaf(v, v, s);
    }
    #pragma unroll
    for (int off = 16; off; off >>= 1)
        s += __shfl_xor_sync(0xffffffffu, s, off);
    if (lane == 0) {
        g_params[w] = s;
        float sc = expf(log_scales[w]);
        sc = fminf(fmaxf(sc, 0.1f), 2.0f);
        g_params[16 + w] = -0.5f / (sc * sc);
    }
}

// ======================= fused cross/aff (mma) + ts partials =================
// grid (TS_CHUNKS, BB), block 512 (16 warps). Block owns 128 tokens.
// Phase A: cross = tok @ centers^T via tf32 mma.sync (BK=32 double buffer);
//   warp pair (w, w+8) splits each chunk's 4 k-steps 2/2; partials combined
//   via smem at the end. Phase B: ts partial accumulation (2 d per thread).
#define XLDP 36
#define XA_WORDS (128 * XLDP)          // 4608 floats
#define XB_WORDS (16 * XLDP)           // 576 floats
#define XBUF (XA_WORDS + XB_WORDS)     // 5184 floats = 20736 B per buffer
#define NKC (DD / 32)                  // 32
#define XCH_OFF 4096                   // float offset of exchange region (16 KB)

__global__ __launch_bounds__(512)
void fused_cross_aff_ts_kernel(const float* __restrict__ tok,
                               const float* __restrict__ centers)
{
    __shared__ float xs[2 * XBUF];     // 41472 B; aliased (saff + xch) after A
    float2 (*saff)[KK] = reinterpret_cast<float2(*)[KK]>(xs);  // [128][16]=16KB
    float* xch = xs + XCH_OFF;         // [8][32][12] floats = 12 KB

    const int tid  = threadIdx.x;
    const int w    = tid >> 5;         // 0..15
    const int lane = tid & 31;
    const int grp  = lane >> 2;        // 0..7
    const int tig  = lane & 3;         // 0..3
    const int wp   = w & 7;            // token group
    const int kh   = w >> 3;           // k-half of the chunk (0: ks 0-1, 1: ks 2-3)
    const int ck   = blockIdx.x;
    const int b    = blockIdx.y;
    const int s0   = ck * TS_SLEN;
    const int bm   = b * SS + s0;      // global token base
    const int wm16 = wp * 16;

    const uint32_t sbase = smem_to_u32(xs);

    // ---------------- Phase A: mma cross products ----------------
    float acc[2][4];
    #pragma unroll
    for (int nf = 0; nf < 2; nf++)
        #pragma unroll
        for (int q = 0; q < 4; q++) acc[nf][q] = 0.f;
    float sq0 = 0.f, sq1 = 0.f;

    // prologue loads: buffer 0, k0 = 0 (512 threads: A 1024 float4 -> 2 each)
    {
        #pragma unroll
        for (int i = 0; i < 2; i++) {
            const int id  = tid + i * 512;
            const int row = id >> 3;
            const int c4  = id & 7;
            CP_ASYNC16(sbase + (uint32_t)(row * XLDP + c4 * 4) * 4,
                       tok + (size_t)(bm + row) * DD + c4 * 4);
        }
        if (tid < 128) {
            const int row = tid >> 3;
            const int c4  = tid & 7;
            CP_ASYNC16(sbase + (uint32_t)(XA_WORDS + row * XLDP + c4 * 4) * 4,
                       centers + (size_t)row * DD + c4 * 4);
        }
        CP_COMMIT();
    }

    for (int kc = 0; kc < NKC; kc++) {
        const int cur = kc & 1;
        if (kc + 1 < NKC) {
            const int nxt = cur ^ 1;
            const uint32_t nb = sbase + (uint32_t)nxt * XBUF * 4;
            const int k0 = (kc + 1) * 32;
            #pragma unroll
            for (int i = 0; i < 2; i++) {
                const int id  = tid + i * 512;
                const int row = id >> 3;
                const int c4  = id & 7;
                CP_ASYNC16(nb + (uint32_t)(row * XLDP + c4 * 4) * 4,
                           tok + (size_t)(bm + row) * DD + k0 + c4 * 4);
            }
            if (tid < 128) {
                const int row = tid >> 3;
                const int c4  = tid & 7;
                CP_ASYNC16(nb + (uint32_t)(XA_WORDS + row * XLDP + c4 * 4) * 4,
                           centers + (size_t)row * DD + k0 + c4 * 4);
            }
            CP_COMMIT();
            CP_WAIT1();
        } else {
            CP_WAIT0();
        }
        __syncthreads();

        const float* As = xs + (size_t)cur * XBUF;
        const float* Bs = As + XA_WORDS;

        #pragma unroll
        for (int ks2 = 0; ks2 < 2; ks2++) {
            const int ks = kh * 2 + ks2;
            const int kq = ks * 8 + tig;
            const float a0 = As[(wm16 + grp)     * XLDP + kq];
            const float a1 = As[(wm16 + grp + 8) * XLDP + kq];
            const float a2 = As[(wm16 + grp)     * XLDP + kq + 4];
            const float a3 = As[(wm16 + grp + 8) * XLDP + kq + 4];
            sq0 = fmaf(a0, a0, fmaf(a2, a2, sq0));
            sq1 = fmaf(a1, a1, fmaf(a3, a3, sq1));
            uint32_t af[4] = {f2tf32(a0), f2tf32(a1), f2tf32(a2), f2tf32(a3)};
            #pragma unroll
            for (int nf = 0; nf < 2; nf++) {
                const int cidx = nf * 8 + grp;
                uint32_t bf[2] = {f2tf32(Bs[cidx * XLDP + kq]),
                                  f2tf32(Bs[cidx * XLDP + kq + 4])};
                mma_tf32(acc[nf], af, bf);
            }
        }
        __syncthreads();
    }

    // ---------------- combine warp-pair partials via smem -------------------
    if (kh == 1) {
        float* p = xch + (size_t)(wp * 32 + lane) * 12;
        #pragma unroll
        for (int nf = 0; nf < 2; nf++)
            #pragma unroll
            for (int q = 0; q < 4; q++) p[nf * 4 + q] = acc[nf][q];
        p[8] = sq0;
        p[9] = sq1;
    }
    __syncthreads();

    if (kh == 0) {
        const float* p = xch + (size_t)(wp * 32 + lane) * 12;
        #pragma unroll
        for (int nf = 0; nf < 2; nf++)
            #pragma unroll
            for (int q = 0; q < 4; q++) acc[nf][q] += p[nf * 4 + q];
        sq0 += p[8];
        sq1 += p[9];

        // tsq: reduce over cols within each quad
        sq0 += __shfl_xor_sync(0xffffffffu, sq0, 1);
        sq0 += __shfl_xor_sync(0xffffffffu, sq0, 2);
        sq1 += __shfl_xor_sync(0xffffffffu, sq1, 1);
        sq1 += __shfl_xor_sync(0xffffffffu, sq1, 2);

        float e0[4], e1[4];
        #pragma unroll
        for (int nf = 0; nf < 2; nf++) {
            #pragma unroll
            for (int j = 0; j < 2; j++) {
                const int col = nf * 8 + tig * 2 + j;
                const float csq = g_params[col];
                const float m   = g_params[16 + col];
                float d0 = fmaxf(sq0 - 2.f * acc[nf][j]     + csq, 0.f);
                float d1 = fmaxf(sq1 - 2.f * acc[nf][2 + j] + csq, 0.f);
                e0[nf * 2 + j] = expf(m * d0);
                e1[nf * 2 + j] = expf(m * d1);
            }
        }
        float es0 = e0[0] + e0[1] + e0[2] + e0[3];
        float es1 = e1[0] + e1[1] + e1[2] + e1[3];
        es0 += __shfl_xor_sync(0xffffffffu, es0, 1);
        es0 += __shfl_xor_sync(0xffffffffu, es0, 2);
        es1 += __shfl_xor_sync(0xffffffffu, es1, 1);
        es1 += __shfl_xor_sync(0xffffffffu, es1, 2);
        const float r0 = 1.f / (es0 + 1e-8f);
        const float r1 = 1.f / (es1 + 1e-8f);

        // write aff to global + smem (aliased over dead xs)
        const int lt0 = wm16 + grp;            // local token 0..127
        #pragma unroll
        for (int nf = 0; nf < 2; nf++) {
            const int col = nf * 8 + tig * 2;
            float v00 = e0[nf * 2] * r0, v01 = e0[nf * 2 + 1] * r0;
            float v10 = e1[nf * 2] * r1, v11 = e1[nf * 2 + 1] * r1;
            *reinterpret_cast<float2*>(g_aff + (size_t)(bm + lt0) * KK + col) =
                make_float2(v00, v01);
            *reinterpret_cast<float2*>(g_aff + (size_t)(bm + lt0 + 8) * KK + col) =
                make_float2(v10, v11);
            saff[lt0][col]     = make_float2(v00, v00);
            saff[lt0][col + 1] = make_float2(v01, v01);
            saff[lt0 + 8][col]     = make_float2(v10, v10);
            saff[lt0 + 8][col + 1] = make_float2(v11, v11);
        }
    }
    __syncthreads();

    // ---------------- Phase B: ts partial accumulation ----------------------
    const int d = tid * 2;             // 2 d-columns per thread (512 threads)
    const float* tp = tok + (size_t)bm * DD + d;

    ull tacc[KK];
    #pragma unroll
    for (int k = 0; k < KK; k++) tacc[k] = 0ull;

    #pragma unroll 4
    for (int s = 0; s < TS_SLEN; s++) {
        float2 v = *reinterpret_cast<const float2*>(tp + (size_t)s * DD);
        ull vp;
        PACK2(vp, v.x, v.y);
        #pragma unroll
        for (int k = 0; k < KK; k++) {
            ull a = *reinterpret_cast<const ull*>(&saff[s][k]);
            FMA2(tacc[k], a, vp);
        }
    }

    float* op = g_tsp + (size_t)ck * MKD + ((size_t)b * KK) * DD + d;
    #pragma unroll
    for (int k = 0; k < KK; k++)
        *reinterpret_cast<ull*>(op + (size_t)k * DD) = tacc[k];
}

// ======================= reduce stage 1: 64 -> 8 partials ====================
__global__ __launch_bounds__(256)
void reduce_stage1_kernel(const float4* __restrict__ src, float4* __restrict__ dst,
                          int len4)
{
    const int i  = blockIdx.x * 256 + threadIdx.x;
    const int pg = blockIdx.y;
    float4 a0 = make_float4(0,0,0,0), a1 = a0;
    #pragma unroll
    for (int q = 0; q < 8; q += 2) {
        float4 v0 = src[(size_t)(pg * 8 + q)     * len4 + i];
        float4 v1 = src[(size_t)(pg * 8 + q + 1) * len4 + i];
        a0.x += v0.x; a0.y += v0.y; a0.z += v0.z; a0.w += v0.w;
        a1.x += v1.x; a1.y += v1.y; a1.z += v1.z; a1.w += v1.w;
    }
    dst[(size_t)pg * len4 + i] = make_float4(a0.x + a1.x, a0.y + a1.y,
                                             a0.z + a1.z, a0.w + a1.w);
}

// ======================= vectorized partial reduce ===========================
__global__ __launch_bounds__(256)
void reduce4_kernel(const float4* __restrict__ src, float4* __restrict__ dst,
                    int np, int len4)
{
    const int i = blockIdx.x * 256 + threadIdx.x;
    if (i >= len4) return;
    float4 a0 = make_float4(0,0,0,0), a1 = a0, a2 = a0, a3 = a0;
    int p = 0;
    for (; p + 4 <= np; p += 4) {
        float4 v0 = src[(size_t)(p + 0) * len4 + i];
        float4 v1 = src[(size_t)(p + 1) * len4 + i];
        float4 v2 = src[(size_t)(p + 2) * len4 + i];
        float4 v3 = src[(size_t)(p + 3) * len4 + i];
        a0.x += v0.x; a0.y += v0.y; a0.z += v0.z; a0.w += v0.w;
        a1.x += v1.x; a1.y += v1.y; a1.z += v1.z; a1.w += v1.w;
        a2.x += v2.x; a2.y += v2.y; a2.z += v2.z; a2.w += v2.w;
        a3.x += v3.x; a3.y += v3.y; a3.z += v3.z; a3.w += v3.w;
    }
    for (; p < np; p++) {
        float4 v = src[(size_t)p * len4 + i];
        a0.x += v.x; a0.y += v.y; a0.z += v.z; a0.w += v.w;
    }
    dst[i] = make_float4(a0.x + a1.x + a2.x + a3.x,
                         a0.y + a1.y + a2.y + a3.y,
                         a0.z + a1.z + a2.z + a3.z,
                         a0.w + a1.w + a2.w + a3.w);
}

// ======================= mini GEMM (R11) =====================================
__global__ __launch_bounds__(256)
void smallgemm_kernel(const float* __restrict__ M64, const float* __restrict__ W)
{
    __shared__ float se[32][66];   // [e][m], padded
    const int tid = threadIdx.x;
    const int n0  = blockIdx.x * 64;
    const int e0  = blockIdx.y * 32;

    {
        const int m  = tid >> 2;
        const int ee = (tid & 3) * 8;
        const float* mp = M64 + (size_t)m * DD + e0 + ee;
        float4 v0 = *reinterpret_cast<const float4*>(mp);
        float4 v1 = *reinterpret_cast<const float4*>(mp + 4);
        se[ee + 0][m] = v0.x; se[ee + 1][m] = v0.y;
        se[ee + 2][m] = v0.z; se[ee + 3][m] = v0.w;
        se[ee + 4][m] = v1.x; se[ee + 5][m] = v1.y;
        se[ee + 6][m] = v1.z; se[ee + 7][m] = v1.w;
    }
    __syncthreads();

    const int nq = tid & 63;
    const int mg = tid >> 6;
    const float* wp = W + (size_t)e0 * DD + n0 + nq;

    ull acc[8];
    #pragma unroll
    for (int j = 0; j < 8; j++) acc[j] = 0ull;

    float wv[4], nv[4];
    #pragma unroll
    for (int q = 0; q < 4; q++) wv[q] = wp[(size_t)q * DD];

    #pragma unroll
    for (int e = 0; e < 32; e += 4) {
        if (e + 4 < 32) {
            #pragma unroll
            for (int q = 0; q < 4; q++) nv[q] = wp[(size_t)(e + 4 + q) * DD];
        }
        #pragma unroll
        for (int q = 0; q < 4; q++) {
            ull wd;
            PACK2(wd, wv[q], wv[q]);
            #pragma unroll
            for (int j = 0; j < 8; j++) {
                ull a = *reinterpret_cast<const ull*>(&se[e + q][mg * 16 + 2 * j]);
                FMA2(acc[j], a, wd);
            }
        }
        #pragma unroll
        for (int q = 0; q < 4; q++) wv[q] = nv[q];
    }

    float* dst = g_ssp + (size_t)blockIdx.y * MKD + n0 + nq;
    #pragma unroll
    for (int j = 0; j < 8; j++) {
        float2 p = *reinterpret_cast<float2*>(&acc[j]);
        dst[(size_t)(mg * 16 + 2 * j)     * DD] = p.x;
        dst[(size_t)(mg * 16 + 2 * j + 1) * DD] = p.y;
    }
}

// ======================= out = aff @ ssw (token-pair packed) =================
__global__ __launch_bounds__(256)
void out_mix_kernel(float* __restrict__ out)
{
    __shared__ float saT[KK][128];   // 8KB, aff transposed
    const int tid  = threadIdx.x;
    const int wid  = tid >> 5;
    const int lane = tid & 31;
    const int b    = blockIdx.y;
    const int s0   = blockIdx.x * 128;

    {
        const float* ap = g_aff + ((size_t)b * SS + s0) * KK;
        #pragma unroll
        for (int it = 0; it < 2; it++) {
            const int i = tid + it * 256;
            float4 v = *reinterpret_cast<const float4*>(ap + i * 4);
            const int t  = i >> 2;
            const int kg = (i & 3) * 4;
            saT[kg + 0][t] = v.x;
            saT[kg + 1][t] = v.y;
            saT[kg + 2][t] = v.z;
            saT[kg + 3][t] = v.w;
        }
    }
    __syncthreads();

    #pragma unroll 1
    for (int pass = 0; pass < 2; pass++) {
        const int d0 = pass * 512 + wid * 64 + lane * 2;

        ull wd0[KK], wd1[KK];
        #pragma unroll
        for (int k = 0; k < KK; k++) {
            float2 wv = *reinterpret_cast<const float2*>(
                g_ssw + ((size_t)(b * KK + k)) * DD + d0);
            PACK2(wd0[k], wv.x, wv.x);
            PACK2(wd1[k], wv.y, wv.y);
        }

        float* op = out + ((size_t)b * SS + s0) * DD + d0;

        #pragma unroll 2
        for (int t = 0; t < 128; t += 2) {
            ull acc0 = 0ull, acc1 = 0ull;
            #pragma unroll
            for (int k = 0; k < KK; k++) {
                ull a = *reinterpret_cast<const ull*>(&saT[k][t]);
                FMA2(acc0, a, wd0[k]);
                FMA2(acc1, a, wd1[k]);
            }
            float2 p0 = *reinterpret_cast<float2*>(&acc0);
            float2 p1 = *reinterpret_cast<float2*>(&acc1);
            *reinterpret_cast<float2*>(op + (size_t)t * DD)       = make_float2(p0.x, p1.x);
            *reinterpret_cast<float2*>(op + (size_t)(t + 1) * DD) = make_float2(p0.y, p1.y);
        }
    }
}

// ======================= launch ==============================================
extern "C" void kernel_launch(void* const* d_in, const int* in_sizes, int n_in,
                              void* d_out, int out_size)
{
    const float* tok     = (const float*)d_in[0];
    const float* centers = (const float*)d_in[1];
    const float* logs    = (const float*)d_in[2];
    const float* Wv      = (const float*)d_in[3];
    const float* Wo      = (const float*)d_in[4];
    float* out = (float*)d_out;

    float *tsp, *ts, *ssp, *ss, *ssw;
    cudaGetSymbolAddress((void**)&tsp, g_tsp);
    cudaGetSymbolAddress((void**)&ts,  g_ts);
    cudaGetSymbolAddress((void**)&ssp, g_ssp);
    cudaGetSymbolAddress((void**)&ss,  g_ss);
    cudaGetSymbolAddress((void**)&ssw, g_ssw);

    const int len4 = MKD / 4;   // 16384

    params_kernel<<<1, 512>>>(centers, logs);

    // affinities (mma) + ts partials, single token pass (512-thread blocks)
    fused_cross_aff_ts_kernel<<<dim3(TS_CHUNKS, BB), 512>>>(tok, centers);

    // ts reduce: 64 -> 8 (into g_ssp) -> 1
    reduce_stage1_kernel<<<dim3(len4 / 256, 8), 256>>>(
        (const float4*)tsp, (float4*)ssp, len4);
    reduce4_kernel<<<len4 / 256, 256>>>(
        (const float4*)ssp, (float4*)ts, 8, len4);

    // ss = ts @ W_v
    smallgemm_kernel<<<dim3(16, SG_ECHUNKS), 256>>>(ts, Wv);
    reduce4_kernel<<<len4 / 256, 256>>>(
        (const float4*)ssp, (float4*)ss, SG_ECHUNKS, len4);

    // ssw = ss @ W_o
    smallgemm_kernel<<<dim3(16, SG_ECHUNKS), 256>>>(ss, Wo);
    reduce4_kernel<<<len4 / 256, 256>>>(
        (const float4*)ssp, (float4*)ssw, SG_ECHUNKS, len4);

    // out = aff @ ssw
    out_mix_kernel<<<dim3(SS / 128, BB), 256>>>(out);
}

// round 16
// speedup vs baseline: 1.1439x; 1.0962x over previous
#include <cuda_runtime.h>
#include <cstdint>

// Problem constants
#define BB 4
#define SS 8192
#define DD 1024
#define KK 16
#define MTOT (BB * SS)        // 32768 tokens
#define TS_CHUNKS 64
#define TS_SLEN (SS / TS_CHUNKS)   // 128
#define MKD (BB * KK * DD)    // 65536
#define SG_ECHUNKS 32         // smallgemm e-chunks (32 e each)

// ---------------- scratch (device globals; no allocations) ------------------
__device__ float g_aff [(size_t)MTOT * KK];            // 2 MB
__device__ float g_tsp [(size_t)TS_CHUNKS * MKD];      // 16 MB  (ts partials)
__device__ float g_ts  [(size_t)MKD];                  // 256 KB (aff^T @ tok)
__device__ float g_ssp [(size_t)SG_ECHUNKS * MKD];     // 8 MB   (mini-gemm partials)
__device__ float g_ss  [(size_t)MKD];                  // 256 KB (ts @ W_v)
__device__ float g_ssw [(size_t)MKD];                  // 256 KB (ss @ W_o)
__device__ float g_params[32];                         // csq[16], m[16]

// ---------------- packed f32x2 helpers ---------------------------------------
#define FMA2(d, a, b) \
    asm("fma.rn.f32x2 %0, %1, %2, %0;" : "+l"(d) : "l"(a), "l"(b))
#define PACK2(dst, lo, hi) \
    asm("mov.b64 %0, {%1, %2};" : "=l"(dst) \
        : "r"(__float_as_uint(lo)), "r"(__float_as_uint(hi)))

typedef unsigned long long ull;

__device__ __forceinline__ uint32_t smem_to_u32(const void* smem_ptr) {
    uint32_t addr;
    asm("{ .reg .u64 tmp; cvta.to.shared.u64 tmp, %1; cvt.u32.u64 %0, tmp; }"
        : "=r"(addr) : "l"(smem_ptr));
    return addr;
}
__device__ __forceinline__ uint32_t f2tf32(float x) {
    uint32_t r;
    asm("cvt.rn.tf32.f32 %0, %1;" : "=r"(r) : "f"(x));
    return r;
}
#define CP_ASYNC16(dst_u32, src_ptr) \
    asm volatile("cp.async.ca.shared.global [%0], [%1], 16;" \
        :: "r"(dst_u32), "l"(src_ptr) : "memory")
#define CP_COMMIT() asm volatile("cp.async.commit_group;" ::: "memory")
#define CP_WAIT0()  asm volatile("cp.async.wait_group 0;" ::: "memory")
#define CP_WAIT1()  asm volatile("cp.async.wait_group 1;" ::: "memory")

__device__ __forceinline__ void mma_tf32(float* c, const uint32_t* a, const uint32_t* b) {
    asm volatile(
        "mma.sync.aligned.m16n8k8.row.col.f32.tf32.tf32.f32 "
        "{%0,%1,%2,%3}, {%4,%5,%6,%7}, {%8,%9}, {%0,%1,%2,%3};\n"
        : "+f"(c[0]), "+f"(c[1]), "+f"(c[2]), "+f"(c[3])
        : "r"(a[0]), "r"(a[1]), "r"(a[2]), "r"(a[3]), "r"(b[0]), "r"(b[1]));
}

// ======================= kernel 0: per-splat params ==========================
__global__ __launch_bounds__(512)
void params_kernel(const float* __restrict__ centers,
                   const float* __restrict__ log_scales)
{
    const int w    = threadIdx.x >> 5;
    const int lane = threadIdx.x & 31;
    float s = 0.f;
    const float* c = centers + (size_t)w * DD;
    for (int d = lane; d < DD; d += 32) {
        float v = c[d];
        s = fmaf(v, v, s);
    }
    #pragma unroll
    for (int off = 16; off; off >>= 1)
        s += __shfl_xor_sync(0xffffffffu, s, off);
    if (lane == 0) {
        g_params[w] = s;
        float sc = expf(log_scales[w]);
        sc = fminf(fmaxf(sc, 0.1f), 2.0f);
        g_params[16 + w] = -0.5f / (sc * sc);
    }
}

// ======================= fused cross/aff (mma) + ts partials (R11 exact) =====
#define XLDP 36
#define XA_WORDS (128 * XLDP)          // 4608 floats
#define XB_WORDS (16 * XLDP)           // 576 floats
#define XBUF (XA_WORDS + XB_WORDS)     // 5184 floats = 20736 B per buffer

__global__ __launch_bounds__(256)
void fused_cross_aff_ts_kernel(const float* __restrict__ tok,
                               const float* __restrict__ centers)
{
    __shared__ float xs[2 * XBUF];     // 41472 B; aliased as saff after phase A
    float2 (*saff)[KK] = reinterpret_cast<float2(*)[KK]>(xs);  // [128][16]

    const int tid  = threadIdx.x;
    const int w    = tid >> 5;
    const int lane = tid & 31;
    const int grp  = lane >> 2;        // 0..7
    const int tig  = lane & 3;         // 0..3
    const int ck   = blockIdx.x;
    const int b    = blockIdx.y;
    const int s0   = ck * TS_SLEN;
    const int bm   = b * SS + s0;      // global token base
    const int wm16 = w * 16;

    const uint32_t sbase = smem_to_u32(xs);

    // ---------------- Phase A: mma cross products ----------------
    float acc[2][4];
    #pragma unroll
    for (int nf = 0; nf < 2; nf++)
        #pragma unroll
        for (int q = 0; q < 4; q++) acc[nf][q] = 0.f;
    float sq0 = 0.f, sq1 = 0.f;

    {
        #pragma unroll
        for (int i = 0; i < 4; i++) {
            const int id  = tid + i * 256;
            const int row = id >> 3;
            const int c4  = id & 7;
            CP_ASYNC16(sbase + (uint32_t)(row * XLDP + c4 * 4) * 4,
                       tok + (size_t)(bm + row) * DD + c4 * 4);
        }
        if (tid < 128) {
            const int row = tid >> 3;
            const int c4  = tid & 7;
            CP_ASYNC16(sbase + (uint32_t)(XA_WORDS + row * XLDP + c4 * 4) * 4,
                       centers + (size_t)row * DD + c4 * 4);
        }
        CP_COMMIT();
    }

    for (int kc = 0; kc < DD / 32; kc++) {
        const int cur = kc & 1;
        if (kc + 1 < DD / 32) {
            const int nxt = cur ^ 1;
            const uint32_t nb = sbase + (uint32_t)nxt * XBUF * 4;
            const int k0 = (kc + 1) * 32;
            #pragma unroll
            for (int i = 0; i < 4; i++) {
                const int id  = tid + i * 256;
                const int row = id >> 3;
                const int c4  = id & 7;
                CP_ASYNC16(nb + (uint32_t)(row * XLDP + c4 * 4) * 4,
                           tok + (size_t)(bm + row) * DD + k0 + c4 * 4);
            }
            if (tid < 128) {
                const int row = tid >> 3;
                const int c4  = tid & 7;
                CP_ASYNC16(nb + (uint32_t)(XA_WORDS + row * XLDP + c4 * 4) * 4,
                           centers + (size_t)row * DD + k0 + c4 * 4);
            }
            CP_COMMIT();
            CP_WAIT1();
        } else {
            CP_WAIT0();
        }
        __syncthreads();

        const float* As = xs + (size_t)cur * XBUF;
        const float* Bs = As + XA_WORDS;

        #pragma unroll
        for (int ks = 0; ks < 4; ks++) {
            const int kq = ks * 8 + tig;
            const float a0 = As[(wm16 + grp)     * XLDP + kq];
            const float a1 = As[(wm16 + grp + 8) * XLDP + kq];
            const float a2 = As[(wm16 + grp)     * XLDP + kq + 4];
            const float a3 = As[(wm16 + grp + 8) * XLDP + kq + 4];
            sq0 = fmaf(a0, a0, fmaf(a2, a2, sq0));
            sq1 = fmaf(a1, a1, fmaf(a3, a3, sq1));
            uint32_t af[4] = {f2tf32(a0), f2tf32(a1), f2tf32(a2), f2tf32(a3)};
            #pragma unroll
            for (int nf = 0; nf < 2; nf++) {
                const int cidx = nf * 8 + grp;
                uint32_t bf[2] = {f2tf32(Bs[cidx * XLDP + kq]),
                                  f2tf32(Bs[cidx * XLDP + kq + 4])};
                mma_tf32(acc[nf], af, bf);
            }
        }
        __syncthreads();
    }

    // tsq: reduce over cols within each quad
    sq0 += __shfl_xor_sync(0xffffffffu, sq0, 1);
    sq0 += __shfl_xor_sync(0xffffffffu, sq0, 2);
    sq1 += __shfl_xor_sync(0xffffffffu, sq1, 1);
    sq1 += __shfl_xor_sync(0xffffffffu, sq1, 2);

    float e0[4], e1[4];
    #pragma unroll
    for (int nf = 0; nf < 2; nf++) {
        #pragma unroll
        for (int j = 0; j < 2; j++) {
            const int col = nf * 8 + tig * 2 + j;
            const float csq = g_params[col];
            const float m   = g_params[16 + col];
            float d0 = fmaxf(sq0 - 2.f * acc[nf][j]     + csq, 0.f);
            float d1 = fmaxf(sq1 - 2.f * acc[nf][2 + j] + csq, 0.f);
            e0[nf * 2 + j] = expf(m * d0);
            e1[nf * 2 + j] = expf(m * d1);
        }
    }
    float es0 = e0[0] + e0[1] + e0[2] + e0[3];
    float es1 = e1[0] + e1[1] + e1[2] + e1[3];
    es0 += __shfl_xor_sync(0xffffffffu, es0, 1);
    es0 += __shfl_xor_sync(0xffffffffu, es0, 2);
    es1 += __shfl_xor_sync(0xffffffffu, es1, 1);
    es1 += __shfl_xor_sync(0xffffffffu, es1, 2);
    const float r0 = 1.f / (es0 + 1e-8f);
    const float r1 = 1.f / (es1 + 1e-8f);

    // write aff to global + smem (aliased over dead xs)
    const int lt0 = wm16 + grp;            // local token 0..127
    #pragma unroll
    for (int nf = 0; nf < 2; nf++) {
        const int col = nf * 8 + tig * 2;
        float v00 = e0[nf * 2] * r0, v01 = e0[nf * 2 + 1] * r0;
        float v10 = e1[nf * 2] * r1, v11 = e1[nf * 2 + 1] * r1;
        *reinterpret_cast<float2*>(g_aff + (size_t)(bm + lt0) * KK + col) =
            make_float2(v00, v01);
        *reinterpret_cast<float2*>(g_aff + (size_t)(bm + lt0 + 8) * KK + col) =
            make_float2(v10, v11);
        saff[lt0][col]     = make_float2(v00, v00);
        saff[lt0][col + 1] = make_float2(v01, v01);
        saff[lt0 + 8][col]     = make_float2(v10, v10);
        saff[lt0 + 8][col + 1] = make_float2(v11, v11);
    }
    __syncthreads();

    // ---------------- Phase B: ts partial accumulation ----------------------
    const int d = tid * 4;
    const float* tp = tok + (size_t)bm * DD + d;

    ull tacc[KK][2];
    #pragma unroll
    for (int k = 0; k < KK; k++) { tacc[k][0] = 0ull; tacc[k][1] = 0ull; }

    #pragma unroll 2
    for (int s = 0; s < TS_SLEN; s++) {
        float4 v = *reinterpret_cast<const float4*>(tp + (size_t)s * DD);
        ull vlo, vhi;
        PACK2(vlo, v.x, v.y);
        PACK2(vhi, v.z, v.w);
        #pragma unroll
        for (int k = 0; k < KK; k++) {
            ull a = *reinterpret_cast<const ull*>(&saff[s][k]);
            FMA2(tacc[k][0], a, vlo);
            FMA2(tacc[k][1], a, vhi);
        }
    }

    float* op = g_tsp + (size_t)ck * MKD + ((size_t)b * KK) * DD + d;
    #pragma unroll
    for (int k = 0; k < KK; k++)
        *reinterpret_cast<ulonglong2*>(op + (size_t)k * DD) =
            make_ulonglong2(tacc[k][0], tacc[k][1]);
}

// ======================= wide partial reduce =================================
// dst4[i] = sum_{p<np} src4[p*len4 + i].
// grid (len4/64), block 256 = 64 i-cols x 4 p-groups; smem combine.
__global__ __launch_bounds__(256)
void reduce_wide_kernel(const float4* __restrict__ src, float4* __restrict__ dst,
                        int np, int len4)
{
    __shared__ float4 red[4][64];
    const int il = threadIdx.x & 63;
    const int pg = threadIdx.x >> 6;          // 0..3
    const int i  = blockIdx.x * 64 + il;
    const int cnt = np >> 2;                  // partials per group

    float4 a0 = make_float4(0, 0, 0, 0), a1 = a0;
    const float4* s = src + (size_t)(pg * cnt) * len4 + i;
    for (int q = 0; q < cnt; q += 2) {
        float4 v0 = s[(size_t)q * len4];
        float4 v1 = s[(size_t)(q + 1) * len4];
        a0.x += v0.x; a0.y += v0.y; a0.z += v0.z; a0.w += v0.w;
        a1.x += v1.x; a1.y += v1.y; a1.z += v1.z; a1.w += v1.w;
    }
    a0.x += a1.x; a0.y += a1.y; a0.z += a1.z; a0.w += a1.w;
    red[pg][il] = a0;
    __syncthreads();

    if (pg == 0) {
        float4 r0 = red[0][il], r1 = red[1][il], r2 = red[2][il], r3 = red[3][il];
        dst[i] = make_float4(r0.x + r1.x + r2.x + r3.x,
                             r0.y + r1.y + r2.y + r3.y,
                             r0.z + r1.z + r2.z + r3.z,
                             r0.w + r1.w + r2.w + r3.w);
    }
}

// ======================= mini GEMM (R11 exact) ===============================
__global__ __launch_bounds__(256)
void smallgemm_kernel(const float* __restrict__ M64, const float* __restrict__ W)
{
    __shared__ float se[32][66];   // [e][m], padded
    const int tid = threadIdx.x;
    const int n0  = blockIdx.x * 64;
    const int e0  = blockIdx.y * 32;

    {
        const int m  = tid >> 2;
        const int ee = (tid & 3) * 8;
        const float* mp = M64 + (size_t)m * DD + e0 + ee;
        float4 v0 = *reinterpret_cast<const float4*>(mp);
        float4 v1 = *reinterpret_cast<const float4*>(mp + 4);
        se[ee + 0][m] = v0.x; se[ee + 1][m] = v0.y;
        se[ee + 2][m] = v0.z; se[ee + 3][m] = v0.w;
        se[ee + 4][m] = v1.x; se[ee + 5][m] = v1.y;
        se[ee + 6][m] = v1.z; se[ee + 7][m] = v1.w;
    }
    __syncthreads();

    const int nq = tid & 63;
    const int mg = tid >> 6;
    const float* wp = W + (size_t)e0 * DD + n0 + nq;

    ull acc[8];
    #pragma unroll
    for (int j = 0; j < 8; j++) acc[j] = 0ull;

    float wv[4], nv[4];
    #pragma unroll
    for (int q = 0; q < 4; q++) wv[q] = wp[(size_t)q * DD];

    #pragma unroll
    for (int e = 0; e < 32; e += 4) {
        if (e + 4 < 32) {
            #pragma unroll
            for (int q = 0; q < 4; q++) nv[q] = wp[(size_t)(e + 4 + q) * DD];
        }
        #pragma unroll
        for (int q = 0; q < 4; q++) {
            ull wd;
            PACK2(wd, wv[q], wv[q]);
            #pragma unroll
            for (int j = 0; j < 8; j++) {
                ull a = *reinterpret_cast<const ull*>(&se[e + q][mg * 16 + 2 * j]);
                FMA2(acc[j], a, wd);
            }
        }
        #pragma unroll
        for (int q = 0; q < 4; q++) wv[q] = nv[q];
    }

    float* dst = g_ssp + (size_t)blockIdx.y * MKD + n0 + nq;
    #pragma unroll
    for (int j = 0; j < 8; j++) {
        float2 p = *reinterpret_cast<float2*>(&acc[j]);
        dst[(size_t)(mg * 16 + 2 * j)     * DD] = p.x;
        dst[(size_t)(mg * 16 + 2 * j + 1) * DD] = p.y;
    }
}

// ======================= out = aff @ ssw (token-pair packed, R11 exact) ======
__global__ __launch_bounds__(256)
void out_mix_kernel(float* __restrict__ out)
{
    __shared__ float saT[KK][128];   // 8KB, aff transposed
    const int tid  = threadIdx.x;
    const int wid  = tid >> 5;
    const int lane = tid & 31;
    const int b    = blockIdx.y;
    const int s0   = blockIdx.x * 128;

    {
        const float* ap = g_aff + ((size_t)b * SS + s0) * KK;
        #pragma unroll
        for (int it = 0; it < 2; it++) {
            const int i = tid + it * 256;
            float4 v = *reinterpret_cast<const float4*>(ap + i * 4);
            const int t  = i >> 2;
            const int kg = (i & 3) * 4;
            saT[kg + 0][t] = v.x;
            saT[kg + 1][t] = v.y;
            saT[kg + 2][t] = v.z;
            saT[kg + 3][t] = v.w;
        }
    }
    __syncthreads();

    #pragma unroll 1
    for (int pass = 0; pass < 2; pass++) {
        const int d0 = pass * 512 + wid * 64 + lane * 2;

        ull wd0[KK], wd1[KK];
        #pragma unroll
        for (int k = 0; k < KK; k++) {
            float2 wv = *reinterpret_cast<const float2*>(
                g_ssw + ((size_t)(b * KK + k)) * DD + d0);
            PACK2(wd0[k], wv.x, wv.x);
            PACK2(wd1[k], wv.y, wv.y);
        }

        float* op = out + ((size_t)b * SS + s0) * DD + d0;

        #pragma unroll 2
        for (int t = 0; t < 128; t += 2) {
            ull acc0 = 0ull, acc1 = 0ull;
            #pragma unroll
            for (int k = 0; k < KK; k++) {
                ull a = *reinterpret_cast<const ull*>(&saT[k][t]);
                FMA2(acc0, a, wd0[k]);
                FMA2(acc1, a, wd1[k]);
            }
            float2 p0 = *reinterpret_cast<float2*>(&acc0);
            float2 p1 = *reinterpret_cast<float2*>(&acc1);
            *reinterpret_cast<float2*>(op + (size_t)t * DD)       = make_float2(p0.x, p1.x);
            *reinterpret_cast<float2*>(op + (size_t)(t + 1) * DD) = make_float2(p0.y, p1.y);
        }
    }
}

// ======================= launch ==============================================
extern "C" void kernel_launch(void* const* d_in, const int* in_sizes, int n_in,
                              void* d_out, int out_size)
{
    const float* tok     = (const float*)d_in[0];
    const float* centers = (const float*)d_in[1];
    const float* logs    = (const float*)d_in[2];
    const float* Wv      = (const float*)d_in[3];
    const float* Wo      = (const float*)d_in[4];
    float* out = (float*)d_out;

    float *tsp, *ts, *ssp, *ss, *ssw;
    cudaGetSymbolAddress((void**)&tsp, g_tsp);
    cudaGetSymbolAddress((void**)&ts,  g_ts);
    cudaGetSymbolAddress((void**)&ssp, g_ssp);
    cudaGetSymbolAddress((void**)&ss,  g_ss);
    cudaGetSymbolAddress((void**)&ssw, g_ssw);

    const int len4 = MKD / 4;   // 16384

    params_kernel<<<1, 512>>>(centers, logs);

    // affinities (mma) + ts partials, single token pass (R11)
    fused_cross_aff_ts_kernel<<<dim3(TS_CHUNKS, BB), 256>>>(tok, centers);

    // ts = sum of 64 partials (single wide reduce)
    reduce_wide_kernel<<<len4 / 64, 256>>>(
        (const float4*)tsp, (float4*)ts, TS_CHUNKS, len4);

    // ss = ts @ W_v
    smallgemm_kernel<<<dim3(16, SG_ECHUNKS), 256>>>(ts, Wv);
    reduce_wide_kernel<<<len4 / 64, 256>>>(
        (const float4*)ssp, (float4*)ss, SG_ECHUNKS, len4);

    // ssw = ss @ W_o
    smallgemm_kernel<<<dim3(16, SG_ECHUNKS), 256>>>(ss, Wo);
    reduce_wide_kernel<<<len4 / 64, 256>>>(
        (const float4*)ssp, (float4*)ssw, SG_ECHUNKS, len4);

    // out = aff @ ssw
    out_mix_kernel<<<dim3(SS / 128, BB), 256>>>(out);
}